// round 9
// baseline (speedup 1.0000x reference)
#include <cuda_runtime.h>
#include <cuda_bf16.h>
#include <cstdint>

#define BATCH 64
#define GM 5184            // 64*81 patches
#define NODES 1296
#define NC 43
#define CO 688             // 43*16

// ---------------- scratch (static device globals; zero-initialized) ----------
__device__ float g_h[BATCH*256*24*24];        // conv1 output
__device__ float g_p[GM*128];                 // prim conv output [m][oc]
__device__ float g_u[BATCH*NODES*8];          // squashed prim caps
__device__ float g_pr[57065472];              // priors [b][n][c][o] (228MB)
__device__ float g_lg[BATCH*NODES*NC];        // routing logits (delta0)
__device__ float g_s[BATCH*CO];               // routing sum (zeroed by sqout)
__device__ float g_o[BATCH*CO];               // routing outputs
__device__ __nv_bfloat16 g_wh[2097152];       // prim weights hi (bf16)
__device__ __nv_bfloat16 g_wl[2097152];       // prim weights lo (bf16)

// ---------------- helpers ----------------------------------------------------
__device__ __forceinline__ uint32_t s2u(const void* p) {
    uint32_t a;
    asm("{ .reg .u64 t; cvta.to.shared.u64 t, %1; cvt.u32.u64 %0, t; }"
        : "=r"(a) : "l"(p));
    return a;
}

#define LDSM4(r, a) asm volatile( \
    "ldmatrix.sync.aligned.m8n8.x4.shared.b16 {%0,%1,%2,%3}, [%4];" \
    : "=r"((r)[0]), "=r"((r)[1]), "=r"((r)[2]), "=r"((r)[3]) : "r"(a))

__device__ __forceinline__ void mma16816(float* c, const uint32_t* a,
                                         uint32_t b0, uint32_t b1) {
    asm volatile(
        "mma.sync.aligned.m16n8k16.row.col.f32.bf16.bf16.f32 "
        "{%0,%1,%2,%3}, {%4,%5,%6,%7}, {%8,%9}, {%0,%1,%2,%3};"
        : "+f"(c[0]), "+f"(c[1]), "+f"(c[2]), "+f"(c[3])
        : "r"(a[0]), "r"(a[1]), "r"(a[2]), "r"(a[3]), "r"(b0), "r"(b1));
}

__device__ __forceinline__ void cvt8(const float* v, uint4& hi, uint4& lo) {
    __nv_bfloat162 h0 = __floats2bfloat162_rn(v[0], v[1]);
    __nv_bfloat162 h1 = __floats2bfloat162_rn(v[2], v[3]);
    __nv_bfloat162 h2 = __floats2bfloat162_rn(v[4], v[5]);
    __nv_bfloat162 h3 = __floats2bfloat162_rn(v[6], v[7]);
    __nv_bfloat162 l0 = __floats2bfloat162_rn(v[0] - __low2float(h0), v[1] - __high2float(h0));
    __nv_bfloat162 l1 = __floats2bfloat162_rn(v[2] - __low2float(h1), v[3] - __high2float(h1));
    __nv_bfloat162 l2 = __floats2bfloat162_rn(v[4] - __low2float(h2), v[5] - __high2float(h2));
    __nv_bfloat162 l3 = __floats2bfloat162_rn(v[6] - __low2float(h3), v[7] - __high2float(h3));
    hi.x = *(uint32_t*)&h0; hi.y = *(uint32_t*)&h1; hi.z = *(uint32_t*)&h2; hi.w = *(uint32_t*)&h3;
    lo.x = *(uint32_t*)&l0; lo.y = *(uint32_t*)&l1; lo.z = *(uint32_t*)&l2; lo.w = *(uint32_t*)&l3;
}

// ---------------- conv1 + relu ----------------------------------------------
__global__ void __launch_bounds__(288) conv1_k(const float* __restrict__ x,
                                               const float* __restrict__ w,
                                               const float* __restrict__ bias) {
    __shared__ __align__(16) float xs[3072];
    __shared__ float ws[4][243];
    int b = blockIdx.x, t = threadIdx.x;
    const float* xb = x + b * 3072;
    for (int j = t; j < 3072; j += 288) xs[j] = xb[j];
    for (int j = t; j < 972; j += 288) {
        int g = j / 243, r = j % 243;
        ws[g][r] = w[(size_t)(blockIdx.y * 4 + g) * 243 + r];
    }
    __syncthreads();
    int g = t / 72, tt = t % 72;
    int oc = blockIdx.y * 4 + g;
    int oy = tt / 3, ox0 = (tt % 3) * 8;
    float bv = bias[oc];
    float a[8];
#pragma unroll
    for (int j = 0; j < 8; j++) a[j] = bv;
#pragma unroll
    for (int ci = 0; ci < 3; ci++) {
#pragma unroll
        for (int ky = 0; ky < 9; ky++) {
            const float* xr = xs + ci * 1024 + (oy + ky) * 32 + ox0;
            float xv[16];
            *(float4*)&xv[0]  = *(const float4*)&xr[0];
            *(float4*)&xv[4]  = *(const float4*)&xr[4];
            *(float4*)&xv[8]  = *(const float4*)&xr[8];
            *(float4*)&xv[12] = *(const float4*)&xr[12];
            const float* wr = ws[g] + ci * 81 + ky * 9;
#pragma unroll
            for (int kx = 0; kx < 9; kx++) {
                float wv = wr[kx];
#pragma unroll
                for (int j = 0; j < 8; j++) a[j] = fmaf(wv, xv[kx + j], a[j]);
            }
        }
    }
    float* hp = g_h + (((size_t)b * 256 + oc) * 24 + oy) * 24 + ox0;
    float4 r0 = make_float4(fmaxf(a[0],0.f), fmaxf(a[1],0.f), fmaxf(a[2],0.f), fmaxf(a[3],0.f));
    float4 r1 = make_float4(fmaxf(a[4],0.f), fmaxf(a[5],0.f), fmaxf(a[6],0.f), fmaxf(a[7],0.f));
    *(float4*)hp = r0;
    *(float4*)(hp + 4) = r1;
}

// ---------------- init p with bias ------------------------------------------
__global__ void pinit_k(const float* __restrict__ pb) {
    int i = blockIdx.x * 256 + threadIdx.x;
    if (i < GM * 128) g_p[i] = pb[i & 127];
}

// ---------------- split prim weights into bf16 hi/lo -------------------------
__global__ void bconv_k(const float* __restrict__ w) {
    int i = blockIdx.x * 256 + threadIdx.x;   // 2097152 total
    float v = w[i];
    __nv_bfloat16 h = __float2bfloat16(v);
    g_wh[i] = h;
    g_wl[i] = __float2bfloat16(v - __bfloat162float(h));
}

// ---------------- primary-caps conv as HMMA GEMM -----------------------------
// M=5184, N=128, K=16384. 128x128 m-tile, K-split 8, 64 tiles of BK=32.
// bf16x3: D += Ah*Bh + Ah*Bl + Al*Bh. 40KB static smem, pitch 80B.
// Single smem buffer + register prefetch of next tile; 2 blocks/SM pinned.
#define SA_H 0
#define SA_L 10240
#define SB_H 20480
#define SB_L 30720

__global__ void __launch_bounds__(256, 2) gemm_h(void) {
    __shared__ __align__(16) char dsm[40960];
    uint32_t sb = s2u(dsm);
    int t = threadIdx.x;
    int m0 = blockIdx.x * 128;
    int kz = blockIdx.y;

    int r = t >> 1, hf = t & 1;
    int mrow = m0 + r;
    bool mv = mrow < GM;
    int bb = mv ? mrow / 81 : 0;
    int s  = mv ? mrow % 81 : 0;
    const float* hbase = g_h + (size_t)bb * 147456 + (2 * (s / 9)) * 24 + 2 * (s % 9);

    int wid = t >> 5, lane = t & 31;
    int wm = wid >> 1, wn = wid & 1;        // 4 x 2 warps over 128m x 128n
    int grp = lane >> 3, rowin = lane & 7;

    float acc[2][8][4];
#pragma unroll
    for (int i = 0; i < 2; i++)
#pragma unroll
        for (int j = 0; j < 8; j++)
#pragma unroll
            for (int q = 0; q < 4; q++) acc[i][j][q] = 0.f;

    float av[2][8];             // prefetched A rows (2 local k-rows x 8)
    uint4 pwh[2], pwl[2];       // prefetched B hi/lo (16 bf16 each)

#define LOADT(kt) do {                                                        \
        int ch = (kt) >> 1;                                                   \
        int kh0 = ((kt) & 1) * 4;                                             \
        const float* ap = hbase + ch * 576;                                   \
        _Pragma("unroll")                                                     \
        for (int k2 = 0; k2 < 2; k2++) {                                      \
            int kh = kh0 + hf * 2 + k2;                                       \
            if (mv) {                                                         \
                const float2* p2 = (const float2*)(ap + kh * 24);             \
                float2 a0 = p2[0], a1 = p2[1], a2 = p2[2], a3 = p2[3];        \
                av[k2][0]=a0.x; av[k2][1]=a0.y; av[k2][2]=a1.x; av[k2][3]=a1.y;\
                av[k2][4]=a2.x; av[k2][5]=a2.y; av[k2][6]=a3.x; av[k2][7]=a3.y;\
            } else {                                                          \
                _Pragma("unroll")                                             \
                for (int j = 0; j < 8; j++) av[k2][j] = 0.f;                  \
            }                                                                 \
        }                                                                     \
        size_t gi = (size_t)r * 16384 + (size_t)ch * 64 + kh0 * 8 + hf * 16;  \
        const uint4* ph = (const uint4*)(g_wh + gi);                          \
        const uint4* pl = (const uint4*)(g_wl + gi);                          \
        pwh[0] = ph[0]; pwh[1] = ph[1];                                       \
        pwl[0] = pl[0]; pwl[1] = pl[1];                                       \
    } while (0)

#define STORET() do {                                                         \
        _Pragma("unroll")                                                     \
        for (int k2 = 0; k2 < 2; k2++) {                                      \
            uint4 hi, lo; cvt8(av[k2], hi, lo);                               \
            int off = r * 80 + (hf * 2 + k2) * 16;                            \
            *(uint4*)(dsm + SA_H + off) = hi;                                 \
            *(uint4*)(dsm + SA_L + off) = lo;                                 \
        }                                                                     \
        int boff = r * 80 + hf * 32;                                          \
        *(uint4*)(dsm + SB_H + boff)      = pwh[0];                           \
        *(uint4*)(dsm + SB_H + boff + 16) = pwh[1];                           \
        *(uint4*)(dsm + SB_L + boff)      = pwl[0];                           \
        *(uint4*)(dsm + SB_L + boff + 16) = pwl[1];                           \
    } while (0)

    LOADT(kz * 64);
    STORET();
    __syncthreads();

    for (int it = 0; it < 64; it++) {
        if (it + 1 < 64) LOADT(kz * 64 + it + 1);   // overlap with compute
#pragma unroll
        for (int ks = 0; ks < 2; ks++) {
            uint32_t ah[2][4], al[2][4];
#pragma unroll
            for (int mt = 0; mt < 2; mt++) {
                uint32_t ra = sb + SA_H +
                    (uint32_t)((wm * 32 + mt * 16 + (grp & 1) * 8 + rowin) * 80 +
                               (ks * 16 + (grp >> 1) * 8) * 2);
                LDSM4(ah[mt], ra);
                LDSM4(al[mt], ra + (SA_L - SA_H));
            }
#pragma unroll
            for (int np = 0; np < 4; np++) {
                uint32_t bh[4], bl[4];
                uint32_t rb = sb + SB_H +
                    (uint32_t)((wn * 64 + np * 16 + (grp >> 1) * 8 + rowin) * 80 +
                               (ks * 16 + (grp & 1) * 8) * 2);
                LDSM4(bh, rb);
                LDSM4(bl, rb + (SB_L - SB_H));
#pragma unroll
                for (int mt = 0; mt < 2; mt++) {
                    mma16816(acc[mt][np * 2],     ah[mt], bh[0], bh[1]);
                    mma16816(acc[mt][np * 2],     ah[mt], bl[0], bl[1]);
                    mma16816(acc[mt][np * 2],     al[mt], bh[0], bh[1]);
                    mma16816(acc[mt][np * 2 + 1], ah[mt], bh[2], bh[3]);
                    mma16816(acc[mt][np * 2 + 1], ah[mt], bl[2], bl[3]);
                    mma16816(acc[mt][np * 2 + 1], al[mt], bh[2], bh[3]);
                }
            }
        }
        __syncthreads();
        if (it + 1 < 64) STORET();
        __syncthreads();
    }
    // ---- epilogue: atomicAdd onto bias-preinitialized g_p ----
#pragma unroll
    for (int mt = 0; mt < 2; mt++) {
        int mA = m0 + wm * 32 + mt * 16 + (lane >> 2);
        int mB = mA + 8;
#pragma unroll
        for (int nf = 0; nf < 8; nf++) {
            int col = wn * 64 + nf * 8 + (lane & 3) * 2;
            if (mA < GM) {
                atomicAdd(g_p + (size_t)mA * 128 + col,     acc[mt][nf][0]);
                atomicAdd(g_p + (size_t)mA * 128 + col + 1, acc[mt][nf][1]);
            }
            if (mB < GM) {
                atomicAdd(g_p + (size_t)mB * 128 + col,     acc[mt][nf][2]);
                atomicAdd(g_p + (size_t)mB * 128 + col + 1, acc[mt][nf][3]);
            }
        }
    }
}

// ---------------- squash primary caps → u -----------------------------------
__global__ void squashu_k() {
    int idx = blockIdx.x * 256 + threadIdx.x;
    if (idx >= BATCH * NODES) return;
    int b = idx / NODES, node = idx % NODES;
    int d = node / 81, sp = node % 81;
    const float* pp = g_p + (size_t)(b * 81 + sp) * 128 + d;
    float v[8], sn = 0.f;
#pragma unroll
    for (int i = 0; i < 8; i++) { v[i] = pp[i * 16]; sn = fmaf(v[i], v[i], sn); }
    float sc = sn / ((1.f + sn) * sqrtf(sn));
    float* up = g_u + (size_t)idx * 8;
#pragma unroll
    for (int i = 0; i < 8; i++) up[i] = v[i] * sc;
}

// ---------------- priors = einsum('bni,ncio->bnco') -------------------------
__global__ void __launch_bounds__(256) priors_k(const float* __restrict__ rw) {
    __shared__ float ws[5504];
    __shared__ __align__(16) float us[512];
    int t = threadIdx.x;
    for (int nn = 0; nn < 4; nn++) {
        int n = blockIdx.x * 4 + nn;
        const float* rwn = rw + (size_t)n * 5504;
        for (int j = t; j < 5504; j += 256) ws[j] = rwn[j];
        for (int j = t; j < 512; j += 256)
            us[j] = g_u[((size_t)(j >> 3) * NODES + n) * 8 + (j & 7)];
        __syncthreads();
        int i0 = t, i1 = t + 256, i2 = t + 512;
        float w0[8], w1[8], w2[8];
#pragma unroll
        for (int i = 0; i < 8; i++) {
            w0[i] = ws[((i0 >> 4) * 8 + i) * 16 + (i0 & 15)];
            w1[i] = ws[((i1 >> 4) * 8 + i) * 16 + (i1 & 15)];
            w2[i] = (i2 < CO) ? ws[((i2 >> 4) * 8 + i) * 16 + (i2 & 15)] : 0.f;
        }
        for (int b = 0; b < 64; b++) {
            float4 ua = *(const float4*)&us[b * 8];
            float4 ub = *(const float4*)&us[b * 8 + 4];
            float u8[8] = {ua.x, ua.y, ua.z, ua.w, ub.x, ub.y, ub.z, ub.w};
            float r0 = 0.f, r1 = 0.f, r2 = 0.f;
#pragma unroll
            for (int i = 0; i < 8; i++) {
                r0 = fmaf(w0[i], u8[i], r0);
                r1 = fmaf(w1[i], u8[i], r1);
                r2 = fmaf(w2[i], u8[i], r2);
            }
            float* dst = g_pr + ((size_t)b * NODES + n) * CO;
            dst[i0] = r0; dst[i1] = r1;
            if (i2 < CO) dst[i2] = r2;
        }
        __syncthreads();
    }
}

// ---------------- pass 0: s = sum_n priors / 43 ------------------------------
__global__ void __launch_bounds__(704) s0_k() {
    int t = threadIdx.x;
    if (t >= CO) return;
    int b = blockIdx.x;
    const float* p = g_pr + ((size_t)b * NODES + blockIdx.y * 108) * CO + t;
    float s0 = 0.f, s1 = 0.f, s2 = 0.f, s3 = 0.f;
    for (int i = 0; i < 108; i += 4) {
        s0 += p[(size_t)(i + 0) * CO];
        s1 += p[(size_t)(i + 1) * CO];
        s2 += p[(size_t)(i + 2) * CO];
        s3 += p[(size_t)(i + 3) * CO];
    }
    atomicAdd(&g_s[b * CO + t], (s0 + s1 + s2 + s3) * (1.f / 43.f));
}

// ---------------- routing pass (iter 1,2): warp-per-node, prefetched ---------
__global__ void __launch_bounds__(256) passw_k(int iter) {
    int t = threadIdx.x, w = t >> 5, l = t & 31;
    int b = blockIdx.x;
    int nbase = blockIdx.y * 216 + w * 27;
    int h = l >> 4;
    float out[22], sacc[22];
    const float* ob = g_o + b * CO;
#pragma unroll
    for (int j = 0; j < 22; j++) {
        int idx = j * 32 + l;
        out[j] = (idx < CO) ? ob[idx] : 0.f;
        sacc[j] = 0.f;
    }
    const float* prbase = g_pr + (size_t)b * NODES * CO;
    float* lgb = g_lg + (size_t)b * NODES * NC;
    float prn[22];
    {
        const float* prow = prbase + (size_t)nbase * CO;
#pragma unroll
        for (int j = 0; j < 22; j++) {
            int idx = j * 32 + l;
            prn[j] = (idx < CO) ? prow[idx] : 0.f;
        }
    }
    for (int n = nbase; n < nbase + 27; n++) {
        float pr[22], lc[22];
#pragma unroll
        for (int j = 0; j < 22; j++) pr[j] = prn[j];
        if (n + 1 < nbase + 27) {
            const float* prow = prbase + (size_t)(n + 1) * CO;
#pragma unroll
            for (int j = 0; j < 22; j++) {
                int idx = j * 32 + l;
                prn[j] = (idx < CO) ? prow[idx] : 0.f;
            }
        }
#pragma unroll
        for (int j = 0; j < 22; j++) {
            float d = pr[j] * out[j];
            d += __shfl_xor_sync(0xffffffffu, d, 8, 16);
            d += __shfl_xor_sync(0xffffffffu, d, 4, 16);
            d += __shfl_xor_sync(0xffffffffu, d, 2, 16);
            d += __shfl_xor_sync(0xffffffffu, d, 1, 16);
            int c = 2 * j + h;
            bool val = c < NC;
            if (iter == 1) {
                if (val && (l & 15) == 0) lgb[n * NC + c] = d;
                lc[j] = val ? d : -1e30f;
            } else {
                lc[j] = val ? (lgb[n * NC + c] + d) : -1e30f;
            }
        }
        float m = -1e30f;
#pragma unroll
        for (int j = 0; j < 22; j++) m = fmaxf(m, lc[j]);
#pragma unroll
        for (int off = 16; off >= 1; off >>= 1)
            m = fmaxf(m, __shfl_xor_sync(0xffffffffu, m, off));
        float ps = 0.f;
#pragma unroll
        for (int j = 0; j < 22; j++) {
            float e = __expf(lc[j] - m);
            lc[j] = e;
            if ((l & 15) != 0) e = 0.f;
            ps += e;
        }
#pragma unroll
        for (int off = 16; off >= 1; off >>= 1)
            ps += __shfl_xor_sync(0xffffffffu, ps, off);
        float inv = 1.f / ps;
#pragma unroll
        for (int j = 0; j < 22; j++)
            sacc[j] = fmaf(lc[j] * inv, pr[j], sacc[j]);
    }
#pragma unroll
    for (int j = 0; j < 22; j++) {
        int idx = j * 32 + l;
        if (idx < CO) atomicAdd(&g_s[b * CO + idx], sacc[j]);
    }
}

// ---------------- squash s → outputs (or final scores) ----------------------
__global__ void __launch_bounds__(704) sqout_k(int final_it, float* __restrict__ outp) {
    int t = threadIdx.x, b = blockIdx.x;
    bool act = t < CO;
    int c = t >> 4, o = t & 15;
    float v = act ? g_s[b * CO + t] : 0.f;
    float q = v * v;
    q += __shfl_xor_sync(0xffffffffu, q, 8, 16);
    q += __shfl_xor_sync(0xffffffffu, q, 4, 16);
    q += __shfl_xor_sync(0xffffffffu, q, 2, 16);
    q += __shfl_xor_sync(0xffffffffu, q, 1, 16);
    if (final_it) {
        if (act && o == 0) outp[b * NC + c] = q / (1.f + q);
    } else {
        if (act) g_o[b * CO + t] = v * (q / ((1.f + q) * sqrtf(q)));
    }
    if (act) g_s[b * CO + t] = 0.f;
}

// ---------------- launch ----------------------------------------------------
extern "C" void kernel_launch(void* const* d_in, const int* in_sizes, int n_in,
                              void* d_out, int out_size) {
    const float* x  = (const float*)d_in[0];
    const float* w1 = (const float*)d_in[1];
    const float* b1 = (const float*)d_in[2];
    const float* pw = (const float*)d_in[3];
    const float* pb = (const float*)d_in[4];
    const float* rw = (const float*)d_in[5];
    float* out = (float*)d_out;

    conv1_k<<<dim3(64, 64), 288>>>(x, w1, b1);
    pinit_k<<<(GM * 128 + 255) / 256, 256>>>(pb);
    bconv_k<<<8192, 256>>>(pw);
    gemm_h<<<dim3(41, 8), 256>>>();
    squashu_k<<<(BATCH * NODES + 255) / 256, 256>>>();
    priors_k<<<324, 256>>>(rw);

    s0_k<<<dim3(64, 12), 704>>>();
    sqout_k<<<64, 704>>>(0, out);
    passw_k<<<dim3(64, 6), 256>>>(1);
    sqout_k<<<64, 704>>>(0, out);
    passw_k<<<dim3(64, 6), 256>>>(2);
    sqout_k<<<64, 704>>>(1, out);
}

// round 10
// speedup vs baseline: 1.2117x; 1.2117x over previous
#include <cuda_runtime.h>
#include <cuda_bf16.h>
#include <cuda_fp16.h>
#include <cstdint>

#define BATCH 64
#define GM 5184            // 64*81 patches
#define NODES 1296
#define NC 43
#define CO 688             // 43*16

// ---------------- scratch (static device globals; zero-initialized) ----------
__device__ float g_h[BATCH*256*24*24];        // conv1 output
__device__ float g_p[GM*128];                 // prim conv output [m][oc]
__device__ float g_u[BATCH*NODES*8];          // squashed prim caps
__device__ __half g_prh[57065472];            // priors fp16 [b][n][c][o] (114MB, L2-resident)
__device__ float g_lg[BATCH*NODES*NC];        // routing logits (delta0)
__device__ float g_s[BATCH*CO];               // routing sum (zeroed by sqout)
__device__ float g_o[BATCH*CO];               // routing outputs
__device__ __nv_bfloat16 g_wh[2097152];       // prim weights hi (bf16)
__device__ __nv_bfloat16 g_wl[2097152];       // prim weights lo (bf16)

// ---------------- helpers ----------------------------------------------------
__device__ __forceinline__ uint32_t s2u(const void* p) {
    uint32_t a;
    asm("{ .reg .u64 t; cvta.to.shared.u64 t, %1; cvt.u32.u64 %0, t; }"
        : "=r"(a) : "l"(p));
    return a;
}

#define LDSM4(r, a) asm volatile( \
    "ldmatrix.sync.aligned.m8n8.x4.shared.b16 {%0,%1,%2,%3}, [%4];" \
    : "=r"((r)[0]), "=r"((r)[1]), "=r"((r)[2]), "=r"((r)[3]) : "r"(a))

__device__ __forceinline__ void mma16816(float* c, const uint32_t* a,
                                         uint32_t b0, uint32_t b1) {
    asm volatile(
        "mma.sync.aligned.m16n8k16.row.col.f32.bf16.bf16.f32 "
        "{%0,%1,%2,%3}, {%4,%5,%6,%7}, {%8,%9}, {%0,%1,%2,%3};"
        : "+f"(c[0]), "+f"(c[1]), "+f"(c[2]), "+f"(c[3])
        : "r"(a[0]), "r"(a[1]), "r"(a[2]), "r"(a[3]), "r"(b0), "r"(b1));
}

__device__ __forceinline__ void cvt8(const float* v, uint4& hi, uint4& lo) {
    __nv_bfloat162 h0 = __floats2bfloat162_rn(v[0], v[1]);
    __nv_bfloat162 h1 = __floats2bfloat162_rn(v[2], v[3]);
    __nv_bfloat162 h2 = __floats2bfloat162_rn(v[4], v[5]);
    __nv_bfloat162 h3 = __floats2bfloat162_rn(v[6], v[7]);
    __nv_bfloat162 l0 = __floats2bfloat162_rn(v[0] - __low2float(h0), v[1] - __high2float(h0));
    __nv_bfloat162 l1 = __floats2bfloat162_rn(v[2] - __low2float(h1), v[3] - __high2float(h1));
    __nv_bfloat162 l2 = __floats2bfloat162_rn(v[4] - __low2float(h2), v[5] - __high2float(h2));
    __nv_bfloat162 l3 = __floats2bfloat162_rn(v[6] - __low2float(h3), v[7] - __high2float(h3));
    hi.x = *(uint32_t*)&h0; hi.y = *(uint32_t*)&h1; hi.z = *(uint32_t*)&h2; hi.w = *(uint32_t*)&h3;
    lo.x = *(uint32_t*)&l0; lo.y = *(uint32_t*)&l1; lo.z = *(uint32_t*)&l2; lo.w = *(uint32_t*)&l3;
}

// f32x2 packed helpers
__device__ __forceinline__ unsigned long long pk2(float lo, float hi) {
    unsigned long long r;
    asm("mov.b64 %0, {%1, %2};" : "=l"(r)
        : "r"(__float_as_uint(lo)), "r"(__float_as_uint(hi)));
    return r;
}
__device__ __forceinline__ unsigned long long dup2(float v) {
    unsigned long long r; unsigned u = __float_as_uint(v);
    asm("mov.b64 %0, {%1, %1};" : "=l"(r) : "r"(u));
    return r;
}
__device__ __forceinline__ void fma2(unsigned long long& d,
                                     unsigned long long a, unsigned long long b) {
    asm("fma.rn.f32x2 %0, %1, %2, %0;" : "+l"(d) : "l"(a), "l"(b));
}
__device__ __forceinline__ void upk2(unsigned long long v, float& lo, float& hi) {
    unsigned a, b;
    asm("mov.b64 {%0, %1}, %2;" : "=r"(a), "=r"(b) : "l"(v));
    lo = __uint_as_float(a); hi = __uint_as_float(b);
}

// ---------------- conv1 + relu (4 oc per thread, packed FFMA2) ---------------
// grid (64 b, 16 oc-groups of 16), block 288 = 4 g x 72 threads.
// Each thread: 4 ocs x 8 outputs. Weights in smem as float2 pairs -> LDS.64
// gives a packed f32x2 operand directly.
__global__ void __launch_bounds__(288) conv1_k(const float* __restrict__ x,
                                               const float* __restrict__ w,
                                               const float* __restrict__ bias) {
    __shared__ __align__(16) float xs[3072];
    __shared__ __align__(8) float2 wsAB[4][243];
    __shared__ __align__(8) float2 wsCD[4][243];
    int b = blockIdx.x, t = threadIdx.x;
    const float* xb = x + b * 3072;
    for (int j = t; j < 3072; j += 288) xs[j] = xb[j];
    for (int j = t; j < 3888; j += 288) {
        int g = j / 972, rem = j % 972;
        int ol = rem / 243, r = rem % 243;
        float val = w[(size_t)(blockIdx.y * 16 + g * 4 + ol) * 243 + r];
        if (ol == 0)      wsAB[g][r].x = val;
        else if (ol == 1) wsAB[g][r].y = val;
        else if (ol == 2) wsCD[g][r].x = val;
        else              wsCD[g][r].y = val;
    }
    __syncthreads();
    int g = t / 72, tt = t % 72;
    int oc0 = blockIdx.y * 16 + g * 4;
    int oy = tt / 3, ox0 = (tt % 3) * 8;
    unsigned long long accAB[8], accCD[8];
    {
        unsigned long long bAB = pk2(bias[oc0], bias[oc0 + 1]);
        unsigned long long bCD = pk2(bias[oc0 + 2], bias[oc0 + 3]);
#pragma unroll
        for (int j = 0; j < 8; j++) { accAB[j] = bAB; accCD[j] = bCD; }
    }
#pragma unroll
    for (int ci = 0; ci < 3; ci++) {
#pragma unroll
        for (int ky = 0; ky < 9; ky++) {
            const float* xr = xs + ci * 1024 + (oy + ky) * 32 + ox0;
            float xv[16];
            *(float4*)&xv[0]  = *(const float4*)&xr[0];
            *(float4*)&xv[4]  = *(const float4*)&xr[4];
            *(float4*)&xv[8]  = *(const float4*)&xr[8];
            *(float4*)&xv[12] = *(const float4*)&xr[12];
            unsigned long long xd[16];
#pragma unroll
            for (int j = 0; j < 16; j++) xd[j] = dup2(xv[j]);
            const float2* wab = &wsAB[g][ci * 81 + ky * 9];
            const float2* wcd = &wsCD[g][ci * 81 + ky * 9];
#pragma unroll
            for (int kx = 0; kx < 9; kx++) {
                unsigned long long wA = *(const unsigned long long*)&wab[kx];
                unsigned long long wC = *(const unsigned long long*)&wcd[kx];
#pragma unroll
                for (int j = 0; j < 8; j++) {
                    fma2(accAB[j], wA, xd[kx + j]);
                    fma2(accCD[j], wC, xd[kx + j]);
                }
            }
        }
    }
    float vA[8], vB[8], vC[8], vD[8];
#pragma unroll
    for (int j = 0; j < 8; j++) {
        upk2(accAB[j], vA[j], vB[j]);
        upk2(accCD[j], vC[j], vD[j]);
    }
#define ST_OC(oi, arr) do {                                                  \
        float* hp = g_h + (((size_t)b * 256 + oc0 + (oi)) * 24 + oy) * 24 + ox0; \
        *(float4*)hp = make_float4(fmaxf(arr[0],0.f), fmaxf(arr[1],0.f),     \
                                   fmaxf(arr[2],0.f), fmaxf(arr[3],0.f));    \
        *(float4*)(hp+4) = make_float4(fmaxf(arr[4],0.f), fmaxf(arr[5],0.f), \
                                       fmaxf(arr[6],0.f), fmaxf(arr[7],0.f));\
    } while (0)
    ST_OC(0, vA); ST_OC(1, vB); ST_OC(2, vC); ST_OC(3, vD);
#undef ST_OC
}

// ---------------- init p with bias ------------------------------------------
__global__ void pinit_k(const float* __restrict__ pb) {
    int i = blockIdx.x * 256 + threadIdx.x;
    if (i < GM * 128) g_p[i] = pb[i & 127];
}

// ---------------- split prim weights into bf16 hi/lo -------------------------
__global__ void bconv_k(const float* __restrict__ w) {
    int i = blockIdx.x * 256 + threadIdx.x;   // 2097152 total
    float v = w[i];
    __nv_bfloat16 h = __float2bfloat16(v);
    g_wh[i] = h;
    g_wl[i] = __float2bfloat16(v - __bfloat162float(h));
}

// ---------------- primary-caps conv as HMMA GEMM (R7 verbatim) ---------------
#define SA_H 0
#define SA_L 10240
#define SB_H 20480
#define SB_L 30720

__global__ void __launch_bounds__(256) gemm_h(void) {
    __shared__ __align__(16) char dsm[40960];
    uint32_t sb = s2u(dsm);
    int t = threadIdx.x;
    int m0 = blockIdx.x * 128;
    int kz = blockIdx.y;

    int r = t >> 1, hf = t & 1;
    int mrow = m0 + r;
    bool mv = mrow < GM;
    int bb = mv ? mrow / 81 : 0;
    int s  = mv ? mrow % 81 : 0;
    const float* hbase = g_h + (size_t)bb * 147456 + (2 * (s / 9)) * 24 + 2 * (s % 9);

    int wid = t >> 5, lane = t & 31;
    int wm = wid >> 1, wn = wid & 1;
    int grp = lane >> 3, rowin = lane & 7;

    float acc[2][8][4];
#pragma unroll
    for (int i = 0; i < 2; i++)
#pragma unroll
        for (int j = 0; j < 8; j++)
#pragma unroll
            for (int q = 0; q < 4; q++) acc[i][j][q] = 0.f;

    for (int it = 0; it < 64; it++) {
        int kt = kz * 64 + it;
        int ch = kt >> 1;
        int kh0 = (kt & 1) * 4;
        {
            const float* ap = hbase + ch * 576;
#pragma unroll
            for (int k2 = 0; k2 < 2; k2++) {
                int kl = hf * 2 + k2;
                int kh = kh0 + kl;
                float v[8];
                if (mv) {
                    const float2* p2 = (const float2*)(ap + kh * 24);
                    float2 a0 = p2[0], a1 = p2[1], a2 = p2[2], a3 = p2[3];
                    v[0]=a0.x; v[1]=a0.y; v[2]=a1.x; v[3]=a1.y;
                    v[4]=a2.x; v[5]=a2.y; v[6]=a3.x; v[7]=a3.y;
                } else {
#pragma unroll
                    for (int j = 0; j < 8; j++) v[j] = 0.f;
                }
                uint4 hi, lo; cvt8(v, hi, lo);
                int off = r * 80 + kl * 16;
                *(uint4*)(dsm + SA_H + off) = hi;
                *(uint4*)(dsm + SA_L + off) = lo;
            }
        }
        {
            size_t gi = (size_t)r * 16384 + ch * 64 + kh0 * 8 + hf * 16;
            const uint4* ph = (const uint4*)(g_wh + gi);
            const uint4* pl = (const uint4*)(g_wl + gi);
            int boff = r * 80 + hf * 32;
            *(uint4*)(dsm + SB_H + boff)      = ph[0];
            *(uint4*)(dsm + SB_H + boff + 16) = ph[1];
            *(uint4*)(dsm + SB_L + boff)      = pl[0];
            *(uint4*)(dsm + SB_L + boff + 16) = pl[1];
        }
        __syncthreads();
#pragma unroll
        for (int ks = 0; ks < 2; ks++) {
            uint32_t ah[2][4], al[2][4], bh[4][4], bl[4][4];
#pragma unroll
            for (int mt = 0; mt < 2; mt++) {
                uint32_t ra = sb + SA_H +
                    (uint32_t)((wm * 32 + mt * 16 + (grp & 1) * 8 + rowin) * 80 +
                               (ks * 16 + (grp >> 1) * 8) * 2);
                LDSM4(ah[mt], ra);
                LDSM4(al[mt], ra + (SA_L - SA_H));
            }
#pragma unroll
            for (int np = 0; np < 4; np++) {
                uint32_t rb = sb + SB_H +
                    (uint32_t)((wn * 64 + np * 16 + (grp >> 1) * 8 + rowin) * 80 +
                               (ks * 16 + (grp & 1) * 8) * 2);
                LDSM4(bh[np], rb);
                LDSM4(bl[np], rb + (SB_L - SB_H));
            }
#pragma unroll
            for (int mt = 0; mt < 2; mt++) {
#pragma unroll
                for (int np = 0; np < 4; np++) {
                    mma16816(acc[mt][np * 2],     ah[mt], bh[np][0], bh[np][1]);
                    mma16816(acc[mt][np * 2],     ah[mt], bl[np][0], bl[np][1]);
                    mma16816(acc[mt][np * 2],     al[mt], bh[np][0], bh[np][1]);
                    mma16816(acc[mt][np * 2 + 1], ah[mt], bh[np][2], bh[np][3]);
                    mma16816(acc[mt][np * 2 + 1], ah[mt], bl[np][2], bl[np][3]);
                    mma16816(acc[mt][np * 2 + 1], al[mt], bh[np][2], bh[np][3]);
                }
            }
        }
        __syncthreads();
    }
#pragma unroll
    for (int mt = 0; mt < 2; mt++) {
        int mA = m0 + wm * 32 + mt * 16 + (lane >> 2);
        int mB = mA + 8;
#pragma unroll
        for (int nf = 0; nf < 8; nf++) {
            int col = wn * 64 + nf * 8 + (lane & 3) * 2;
            if (mA < GM) {
                atomicAdd(g_p + (size_t)mA * 128 + col,     acc[mt][nf][0]);
                atomicAdd(g_p + (size_t)mA * 128 + col + 1, acc[mt][nf][1]);
            }
            if (mB < GM) {
                atomicAdd(g_p + (size_t)mB * 128 + col,     acc[mt][nf][2]);
                atomicAdd(g_p + (size_t)mB * 128 + col + 1, acc[mt][nf][3]);
            }
        }
    }
}

// ---------------- squash primary caps → u -----------------------------------
__global__ void squashu_k() {
    int idx = blockIdx.x * 256 + threadIdx.x;
    if (idx >= BATCH * NODES) return;
    int b = idx / NODES, node = idx % NODES;
    int d = node / 81, sp = node % 81;
    const float* pp = g_p + (size_t)(b * 81 + sp) * 128 + d;
    float v[8], sn = 0.f;
#pragma unroll
    for (int i = 0; i < 8; i++) { v[i] = pp[i * 16]; sn = fmaf(v[i], v[i], sn); }
    float sc = sn / ((1.f + sn) * sqrtf(sn));
    float* up = g_u + (size_t)idx * 8;
#pragma unroll
    for (int i = 0; i < 8; i++) up[i] = v[i] * sc;
}

// ---------------- priors = einsum('bni,ncio->bnco') -> fp16 ------------------
__global__ void __launch_bounds__(256) priors_k(const float* __restrict__ rw) {
    __shared__ float ws[5504];
    __shared__ __align__(16) float us[512];
    int t = threadIdx.x;
    for (int nn = 0; nn < 4; nn++) {
        int n = blockIdx.x * 4 + nn;
        const float* rwn = rw + (size_t)n * 5504;
        for (int j = t; j < 5504; j += 256) ws[j] = rwn[j];
        for (int j = t; j < 512; j += 256)
            us[j] = g_u[((size_t)(j >> 3) * NODES + n) * 8 + (j & 7)];
        __syncthreads();
        int i0 = t, i1 = t + 256, i2 = t + 512;
        float w0[8], w1[8], w2[8];
#pragma unroll
        for (int i = 0; i < 8; i++) {
            w0[i] = ws[((i0 >> 4) * 8 + i) * 16 + (i0 & 15)];
            w1[i] = ws[((i1 >> 4) * 8 + i) * 16 + (i1 & 15)];
            w2[i] = (i2 < CO) ? ws[((i2 >> 4) * 8 + i) * 16 + (i2 & 15)] : 0.f;
        }
        for (int b = 0; b < 64; b++) {
            float4 ua = *(const float4*)&us[b * 8];
            float4 ub = *(const float4*)&us[b * 8 + 4];
            float u8[8] = {ua.x, ua.y, ua.z, ua.w, ub.x, ub.y, ub.z, ub.w};
            float r0 = 0.f, r1 = 0.f, r2 = 0.f;
#pragma unroll
            for (int i = 0; i < 8; i++) {
                r0 = fmaf(w0[i], u8[i], r0);
                r1 = fmaf(w1[i], u8[i], r1);
                r2 = fmaf(w2[i], u8[i], r2);
            }
            __half* dst = g_prh + ((size_t)b * NODES + n) * CO;
            dst[i0] = __float2half_rn(r0);
            dst[i1] = __float2half_rn(r1);
            if (i2 < CO) dst[i2] = __float2half_rn(r2);
        }
        __syncthreads();
    }
}

// ---------------- pass 0: s = sum_n priors / 43 ------------------------------
__global__ void __launch_bounds__(704) s0_k() {
    int t = threadIdx.x;
    if (t >= CO) return;
    int b = blockIdx.x;
    const __half* p = g_prh + ((size_t)b * NODES + blockIdx.y * 108) * CO + t;
    float s0 = 0.f, s1 = 0.f, s2 = 0.f, s3 = 0.f;
    for (int i = 0; i < 108; i += 4) {
        s0 += __half2float(p[(size_t)(i + 0) * CO]);
        s1 += __half2float(p[(size_t)(i + 1) * CO]);
        s2 += __half2float(p[(size_t)(i + 2) * CO]);
        s3 += __half2float(p[(size_t)(i + 3) * CO]);
    }
    atomicAdd(&g_s[b * CO + t], (s0 + s1 + s2 + s3) * (1.f / 43.f));
}

// ---------------- routing pass (iter 1,2): warp-per-node (R7 structure) ------
__global__ void __launch_bounds__(256) passw_k(int iter) {
    int t = threadIdx.x, w = t >> 5, l = t & 31;
    int b = blockIdx.x;
    int nbase = blockIdx.y * 216 + w * 27;
    int h = l >> 4;
    float out[22], sacc[22];
    const float* ob = g_o + b * CO;
#pragma unroll
    for (int j = 0; j < 22; j++) {
        int idx = j * 32 + l;
        out[j] = (idx < CO) ? ob[idx] : 0.f;
        sacc[j] = 0.f;
    }
    const __half* prbase = g_prh + (size_t)b * NODES * CO;
    float* lgb = g_lg + (size_t)b * NODES * NC;
    for (int n = nbase; n < nbase + 27; n++) {
        const __half* prow = prbase + (size_t)n * CO;
        float pr[22], lc[22];
#pragma unroll
        for (int j = 0; j < 22; j++) {
            int idx = j * 32 + l;
            pr[j] = (idx < CO) ? __half2float(prow[idx]) : 0.f;
        }
#pragma unroll
        for (int j = 0; j < 22; j++) {
            float d = pr[j] * out[j];
            d += __shfl_xor_sync(0xffffffffu, d, 8, 16);
            d += __shfl_xor_sync(0xffffffffu, d, 4, 16);
            d += __shfl_xor_sync(0xffffffffu, d, 2, 16);
            d += __shfl_xor_sync(0xffffffffu, d, 1, 16);
            int c = 2 * j + h;
            bool val = c < NC;
            if (iter == 1) {
                if (val && (l & 15) == 0) lgb[n * NC + c] = d;
                lc[j] = val ? d : -1e30f;
            } else {
                lc[j] = val ? (lgb[n * NC + c] + d) : -1e30f;
            }
        }
        float m = -1e30f;
#pragma unroll
        for (int j = 0; j < 22; j++) m = fmaxf(m, lc[j]);
#pragma unroll
        for (int off = 16; off >= 1; off >>= 1)
            m = fmaxf(m, __shfl_xor_sync(0xffffffffu, m, off));
        float ps = 0.f;
#pragma unroll
        for (int j = 0; j < 22; j++) {
            float e = __expf(lc[j] - m);
            lc[j] = e;
            if ((l & 15) != 0) e = 0.f;
            ps += e;
        }
#pragma unroll
        for (int off = 16; off >= 1; off >>= 1)
            ps += __shfl_xor_sync(0xffffffffu, ps, off);
        float inv = 1.f / ps;
#pragma unroll
        for (int j = 0; j < 22; j++)
            sacc[j] = fmaf(lc[j] * inv, pr[j], sacc[j]);
    }
#pragma unroll
    for (int j = 0; j < 22; j++) {
        int idx = j * 32 + l;
        if (idx < CO) atomicAdd(&g_s[b * CO + idx], sacc[j]);
    }
}

// ---------------- squash s → outputs (or final scores) ----------------------
__global__ void __launch_bounds__(704) sqout_k(int final_it, float* __restrict__ outp) {
    int t = threadIdx.x, b = blockIdx.x;
    bool act = t < CO;
    int c = t >> 4, o = t & 15;
    float v = act ? g_s[b * CO + t] : 0.f;
    float q = v * v;
    q += __shfl_xor_sync(0xffffffffu, q, 8, 16);
    q += __shfl_xor_sync(0xffffffffu, q, 4, 16);
    q += __shfl_xor_sync(0xffffffffu, q, 2, 16);
    q += __shfl_xor_sync(0xffffffffu, q, 1, 16);
    if (final_it) {
        if (act && o == 0) outp[b * NC + c] = q / (1.f + q);
    } else {
        if (act) g_o[b * CO + t] = v * (q / ((1.f + q) * sqrtf(q)));
    }
    if (act) g_s[b * CO + t] = 0.f;
}

// ---------------- launch ----------------------------------------------------
extern "C" void kernel_launch(void* const* d_in, const int* in_sizes, int n_in,
                              void* d_out, int out_size) {
    const float* x  = (const float*)d_in[0];
    const float* w1 = (const float*)d_in[1];
    const float* b1 = (const float*)d_in[2];
    const float* pw = (const float*)d_in[3];
    const float* pb = (const float*)d_in[4];
    const float* rw = (const float*)d_in[5];
    float* out = (float*)d_out;

    conv1_k<<<dim3(64, 16), 288>>>(x, w1, b1);
    pinit_k<<<(GM * 128 + 255) / 256, 256>>>(pb);
    bconv_k<<<8192, 256>>>(pw);
    gemm_h<<<dim3(41, 8), 256>>>();
    squashu_k<<<(BATCH * NODES + 255) / 256, 256>>>();
    priors_k<<<324, 256>>>(rw);

    s0_k<<<dim3(64, 12), 704>>>();
    sqout_k<<<64, 704>>>(0, out);
    passw_k<<<dim3(64, 6), 256>>>(1);
    sqout_k<<<64, 704>>>(0, out);
    passw_k<<<dim3(64, 6), 256>>>(2);
    sqout_k<<<64, 704>>>(1, out);
}